// round 5
// baseline (speedup 1.0000x reference)
#include <cuda_runtime.h>
#include <cuda_bf16.h>
#include <cstdint>
#include <math.h>

#define NSTEPS 100
#define NU     128
#define BTOT   200000
#define NTHREADS 288
// CTA handles three 64-row tiles = 192 samples
#define CTA_SAMPLES 192
#define NSLOTS 302

// ---------------- SMEM layout ----------------
// H1[3] tiles at 0, H2[3] tiles at 49152, float region at 98304
#define SM_H1   0
#define SM_H2   49152
#define SM_F32  98304

// float indices within fA
#define F_W0A   0
#define F_W0B   128
#define F_W3A   256
#define F_W3B   384
#define F_BE0   512      // [2][128] parity ping-pong
#define F_BE1   768
#define F_BE2   1024
#define F_COEF  1280     // indexed by t
#define F_INVAS 1380
#define F_BSQ   1480
#define F_B3    1580     // 2 floats (pad to 1584)
#define F_PP    1584     // float2 [3 tiles][4 warps][64 rows] = 1536 floats
#define F_TOTAL 3120
#define SMEM_TOTAL (SM_F32 + F_TOTAL * 4)   // 110784 bytes

// ---------------- helpers ----------------
static __device__ __forceinline__ uint32_t smem_u32(const void* p) {
    uint32_t a;
    asm("{ .reg .u64 t; cvta.to.shared.u64 t, %1; cvt.u32.u64 %0, t; }" : "=r"(a) : "l"(p));
    return a;
}
static __device__ __forceinline__ uint32_t pack_bf16(float lo, float hi) {
    __nv_bfloat162 h = __floats2bfloat162_rn(lo, hi);
    return *reinterpret_cast<uint32_t*>(&h);
}

#define LDSM4(r0, r1, r2, r3, addr)                                              \
    asm volatile("ldmatrix.sync.aligned.m8n8.x4.shared.b16 {%0,%1,%2,%3}, [%4];" \
                 : "=r"(r0), "=r"(r1), "=r"(r2), "=r"(r3) : "r"(addr))

static __device__ __forceinline__ void mma16816(float c[4],
        uint32_t a0, uint32_t a1, uint32_t a2, uint32_t a3,
        uint32_t b0, uint32_t b1) {
    asm volatile(
        "mma.sync.aligned.m16n8k16.row.col.f32.bf16.bf16.f32 "
        "{%0,%1,%2,%3}, {%4,%5,%6,%7}, {%8,%9}, {%0,%1,%2,%3};"
        : "+f"(c[0]), "+f"(c[1]), "+f"(c[2]), "+f"(c[3])
        : "r"(a0), "r"(a1), "r"(a2), "r"(a3), "r"(b0), "r"(b1));
}

static __device__ __forceinline__ void sts128v(uint32_t addr, uint32_t a, uint32_t b,
                                               uint32_t c, uint32_t d) {
    asm volatile("st.shared.v4.b32 [%0], {%1,%2,%3,%4};"
                 :: "r"(addr), "r"(a), "r"(b), "r"(c), "r"(d) : "memory");
}
static __device__ __forceinline__ void sts32(uint32_t addr, uint32_t v) {
    asm volatile("st.shared.b32 [%0], %1;" :: "r"(addr), "r"(v) : "memory");
}

// ---- G1: dst = relu(src @ W + be), 64x128x128, warp owns 32 N-cols ----
static __device__ __forceinline__ void gemm_g1(
    uint32_t srcb, uint32_t dstb, const uint32_t (&B)[4][8][2], const float* be,
    int wg, uint32_t lrowoff, uint32_t r_lo, uint32_t khalf,
    uint32_t erow, uint32_t ecolq)
{
    #pragma unroll 1
    for (int mt = 0; mt < 4; mt++) {
        float c[4][4];
        #pragma unroll
        for (int nt = 0; nt < 4; nt++)
            #pragma unroll
            for (int q = 0; q < 4; q++) c[nt][q] = 0.f;

        const uint32_t abase = srcb + (uint32_t)mt * 4096 + lrowoff;
        #pragma unroll
        for (int kc = 0; kc < 8; kc++) {
            uint32_t a0, a1, a2, a3;
            LDSM4(a0, a1, a2, a3, abase + ((((uint32_t)(kc * 2) + khalf) ^ r_lo) << 4));
            #pragma unroll
            for (int nt = 0; nt < 4; nt++)
                mma16816(c[nt], a0, a1, a2, a3, B[nt][kc][0], B[nt][kc][1]);
        }
        const uint32_t row0 = (uint32_t)mt * 16 + erow;
        const uint32_t dst0 = dstb + row0 * 256;
        #pragma unroll
        for (int nt = 0; nt < 4; nt++) {
            int col = wg * 32 + nt * 8 + (int)ecolq * 2;
            float bea = be[col], beb = be[col + 1];
            float v0 = fmaxf(c[nt][0] + bea, 0.f);
            float v1 = fmaxf(c[nt][1] + beb, 0.f);
            float v2 = fmaxf(c[nt][2] + bea, 0.f);
            float v3 = fmaxf(c[nt][3] + beb, 0.f);
            uint32_t chunk = (uint32_t)(wg * 4 + nt);
            uint32_t a0addr = dst0 + ((chunk ^ erow) << 4) + ecolq * 4;
            sts32(a0addr,        pack_bf16(v0, v1));
            sts32(a0addr + 2048, pack_bf16(v2, v3));
        }
    }
}

// ---- G2 + fused layer3 dot: per-warp pred partials -> fPPt ----
static __device__ __forceinline__ void gemm_g2(
    uint32_t srcb, const uint32_t (&B)[4][8][2], const float* be,
    const float* w3a, const float* w3b, float2* fPPt,
    int wg, uint32_t lrowoff, uint32_t r_lo, uint32_t khalf,
    uint32_t erow, uint32_t ecolq)
{
    #pragma unroll 1
    for (int mt = 0; mt < 4; mt++) {
        float c[4][4];
        #pragma unroll
        for (int nt = 0; nt < 4; nt++)
            #pragma unroll
            for (int q = 0; q < 4; q++) c[nt][q] = 0.f;

        const uint32_t abase = srcb + (uint32_t)mt * 4096 + lrowoff;
        #pragma unroll
        for (int kc = 0; kc < 8; kc++) {
            uint32_t a0, a1, a2, a3;
            LDSM4(a0, a1, a2, a3, abase + ((((uint32_t)(kc * 2) + khalf) ^ r_lo) << 4));
            #pragma unroll
            for (int nt = 0; nt < 4; nt++)
                mma16816(c[nt], a0, a1, a2, a3, B[nt][kc][0], B[nt][kc][1]);
        }

        float pA0 = 0.f, pA1 = 0.f, pB0 = 0.f, pB1 = 0.f;
        #pragma unroll
        for (int nt = 0; nt < 4; nt++) {
            int col = wg * 32 + nt * 8 + (int)ecolq * 2;
            float bea = be[col], beb = be[col + 1];
            float wa0 = w3a[col], wa1 = w3a[col + 1];
            float wb0 = w3b[col], wb1 = w3b[col + 1];
            float v0 = fmaxf(c[nt][0] + bea, 0.f);
            float v1 = fmaxf(c[nt][1] + beb, 0.f);
            float v2 = fmaxf(c[nt][2] + bea, 0.f);
            float v3 = fmaxf(c[nt][3] + beb, 0.f);
            pA0 = fmaf(v0, wa0, fmaf(v1, wa1, pA0));
            pA1 = fmaf(v0, wb0, fmaf(v1, wb1, pA1));
            pB0 = fmaf(v2, wa0, fmaf(v3, wa1, pB0));
            pB1 = fmaf(v2, wb0, fmaf(v3, wb1, pB1));
        }
        pA0 += __shfl_xor_sync(0xffffffffu, pA0, 1);
        pA1 += __shfl_xor_sync(0xffffffffu, pA1, 1);
        pB0 += __shfl_xor_sync(0xffffffffu, pB0, 1);
        pB1 += __shfl_xor_sync(0xffffffffu, pB1, 1);
        pA0 += __shfl_xor_sync(0xffffffffu, pA0, 2);
        pA1 += __shfl_xor_sync(0xffffffffu, pA1, 2);
        pB0 += __shfl_xor_sync(0xffffffffu, pB0, 2);
        pB1 += __shfl_xor_sync(0xffffffffu, pB1, 2);
        if (ecolq == 0) {
            int r = mt * 16 + (int)erow;
            fPPt[wg * 64 + r]     = make_float2(pA0, pA1);
            fPPt[wg * 64 + r + 8] = make_float2(pB0, pB1);
        }
    }
}

// ---- layer0, one full 128-col row ----
static __device__ __forceinline__ void layer0_full(
    uint32_t h1buf, float2 xv, const float* fA, const float* be0, int row)
{
    const uint32_t rowbase = h1buf + (uint32_t)row * 256;
    const uint32_t rx = (uint32_t)(row & 7);
    #pragma unroll
    for (int c8 = 0; c8 < 16; c8++) {
        int j = c8 * 8;
        float4 wa0 = *(const float4*)&fA[F_W0A + j];
        float4 wa1 = *(const float4*)&fA[F_W0A + j + 4];
        float4 wb0 = *(const float4*)&fA[F_W0B + j];
        float4 wb1 = *(const float4*)&fA[F_W0B + j + 4];
        float4 b0v = *(const float4*)&be0[j];
        float4 b1v = *(const float4*)&be0[j + 4];
        float v0 = fmaxf(fmaf(xv.x, wa0.x, fmaf(xv.y, wb0.x, b0v.x)), 0.f);
        float v1 = fmaxf(fmaf(xv.x, wa0.y, fmaf(xv.y, wb0.y, b0v.y)), 0.f);
        float v2 = fmaxf(fmaf(xv.x, wa0.z, fmaf(xv.y, wb0.z, b0v.z)), 0.f);
        float v3 = fmaxf(fmaf(xv.x, wa0.w, fmaf(xv.y, wb0.w, b0v.w)), 0.f);
        float v4 = fmaxf(fmaf(xv.x, wa1.x, fmaf(xv.y, wb1.x, b1v.x)), 0.f);
        float v5 = fmaxf(fmaf(xv.x, wa1.y, fmaf(xv.y, wb1.y, b1v.y)), 0.f);
        float v6 = fmaxf(fmaf(xv.x, wa1.z, fmaf(xv.y, wb1.z, b1v.z)), 0.f);
        float v7 = fmaxf(fmaf(xv.x, wa1.w, fmaf(xv.y, wb1.w, b1v.w)), 0.f);
        uint32_t addr = rowbase + ((((uint32_t)c8) ^ rx) << 4);
        sts128v(addr, pack_bf16(v0, v1), pack_bf16(v2, v3),
                      pack_bf16(v4, v5), pack_bf16(v6, v7));
    }
}

__global__ void __launch_bounds__(NTHREADS, 2)
ddpm_kernel(const float* __restrict__ noise, const float* __restrict__ z,
            const float* __restrict__ W0, const float* __restrict__ b0,
            const float* __restrict__ W1, const float* __restrict__ b1,
            const float* __restrict__ W2, const float* __restrict__ b2,
            const float* __restrict__ W3, const float* __restrict__ b3,
            const float* __restrict__ E0, const float* __restrict__ E1,
            const float* __restrict__ E2, float* __restrict__ out)
{
    extern __shared__ char smem_raw[];
    const uint32_t sb = smem_u32(smem_raw);
    float* fA = (float*)(smem_raw + SM_F32);
    float2* fPP = (float2*)&fA[F_PP];

    const int tid  = threadIdx.x;
    const int lane = tid & 31;
    const int wid  = tid >> 5;
    const int base = blockIdx.x * CTA_SAMPLES;

    // ---- prologue: small tensors ----
    if (tid < 128) {
        fA[F_W0A + tid] = W0[tid];
        fA[F_W0B + tid] = W0[NU + tid];
        fA[F_W3A + tid] = W3[2 * tid];
        fA[F_W3B + tid] = W3[2 * tid + 1];
        // step 0 (t=99) tables, parity 0
        fA[F_BE0 + tid] = b0[tid] + E0[99 * NU + tid];
        fA[F_BE1 + tid] = b1[tid] + E1[99 * NU + tid];
        fA[F_BE2 + tid] = b2[tid] + E2[99 * NU + tid];
    }
    if (tid < 2) fA[F_B3 + tid] = b3[tid];
    if (tid == 0) {
        double prod = 1.0;
        for (int t = 0; t < NSTEPS; t++) {
            double xl = -6.0 + 12.0 * (double)t / 99.0;
            double beta = (1.0 / (1.0 + exp(-xl))) * (0.005 - 1e-5) + 1e-5;
            double alpha = 1.0 - beta;
            prod *= alpha;
            fA[F_COEF + t]  = (float)(beta / sqrt(1.0 - prod));
            fA[F_INVAS + t] = (float)(1.0 / sqrt(alpha));
            fA[F_BSQ + t]   = (float)sqrt(beta);
        }
    }

    // ---- weight fragments: warps 0-3 <- W1, warps 4-7 <- W2 ----
    uint32_t Bw[4][8][2];
    const int wg = wid & 3;
    if (wid < 8) {
        const float* Wsrc = (wid < 4) ? W1 : W2;
        const int n0 = wg * 32 + (lane >> 2);
        const int kb2 = (lane & 3) * 2;
        #pragma unroll
        for (int nt = 0; nt < 4; nt++) {
            int n = n0 + nt * 8;
            #pragma unroll
            for (int kc = 0; kc < 8; kc++) {
                int k0 = kc * 16 + kb2;
                Bw[nt][kc][0] = pack_bf16(Wsrc[k0 * NU + n],       Wsrc[(k0 + 1) * NU + n]);
                Bw[nt][kc][1] = pack_bf16(Wsrc[(k0 + 8) * NU + n], Wsrc[(k0 + 9) * NU + n]);
            }
        }
    }

    // ---- scalar warp x-state in registers: xreg[tile][rowpair] ----
    float2 xreg[3][2];
    float2 zuse[2] = {make_float2(0.f, 0.f), make_float2(0.f, 0.f)};
    const int sidx = tid - 256;   // 0..31 for scalar warp
    if (wid == 8) {
        #pragma unroll
        for (int tt = 0; tt < 3; tt++) {
            #pragma unroll
            for (int ri = 0; ri < 2; ri++) {
                int smp = base + tt * 64 + sidx + ri * 32;
                xreg[tt][ri] = (smp < BTOT) ? ((const float2*)noise)[smp]
                                            : make_float2(0.f, 0.f);
            }
        }
    }

    // per-lane ldmatrix / epilogue constants
    const uint32_t r_lo    = (uint32_t)(lane & 7);
    const uint32_t half_l  = (uint32_t)((lane >> 3) & 1);
    const uint32_t khalf   = (uint32_t)(lane >> 4);
    const uint32_t lrowoff = (half_l * 8 + r_lo) * 256;
    const uint32_t erow    = (uint32_t)(lane >> 2);
    const uint32_t ecolq   = (uint32_t)(lane & 3);

    __syncthreads();

    // ---- initial layer0 for all 3 tiles, step 0 ----
    if (tid < 192) {
        int tt  = tid >> 6;
        int row = tid & 63;
        int smp = base + tt * 64 + row;
        float2 xv = (smp < BTOT) ? ((const float2*)noise)[smp] : make_float2(0.f, 0.f);
        layer0_full(sb + SM_H1 + tt * 16384, xv, fA, &fA[F_BE0], row);
    }
    __syncthreads();

    // ---- slot loop ----
    int sm3 = 0, kdiv3 = 0;
    #pragma unroll 1
    for (int s = 0; s < NSLOTS; s++) {
        const int tg = sm3;
        const int tb = (sm3 + 2 >= 3) ? sm3 - 1 : sm3 + 2;
        const int tc = (sm3 + 1 >= 3) ? sm3 - 2 : sm3 + 1;
        const int kg = kdiv3;
        const int kb = (sm3 == 0) ? kdiv3 - 1 : kdiv3;
        const int kc = (sm3 == 2) ? kdiv3 : kdiv3 - 1;

        if (wid < 4) {
            // -------- G1 on tile tg, step kg --------
            if (kg < NSTEPS) {
                gemm_g1(sb + SM_H1 + tg * 16384, sb + SM_H2 + tg * 16384, Bw,
                        &fA[F_BE1 + (kg & 1) * 128], wg,
                        lrowoff, r_lo, khalf, erow, ecolq);
            }
        } else if (wid < 8) {
            // -------- G2 on tile tb, step kb --------
            if (kb >= 0 && kb < NSTEPS) {
                gemm_g2(sb + SM_H2 + tb * 16384, Bw,
                        &fA[F_BE2 + (kb & 1) * 128],
                        &fA[F_W3A], &fA[F_W3B], &fPP[tb * 256], wg,
                        lrowoff, r_lo, khalf, erow, ecolq);
            }
        } else {
            // -------- scalar warp --------
            // 1) z prefetch for next slot's update (tile tb, step kb)
            float2 znew[2] = {make_float2(0.f, 0.f), make_float2(0.f, 0.f)};
            if (kb >= 0 && kb < NSTEPS) {
                #pragma unroll
                for (int ri = 0; ri < 2; ri++) {
                    int smp = base + tb * 64 + sidx + ri * 32;
                    if (smp < BTOT)
                        znew[ri] = ((const float2*)z)[(size_t)kb * BTOT + smp];
                }
            }
            // 2) next-step table prefetch (at sm3==1)
            if (sm3 == 1 && kdiv3 + 1 < NSTEPS) {
                int kn = kdiv3 + 1;
                int tn = 99 - kn;
                int p  = (kn & 1) * 128;
                #pragma unroll
                for (int q = 0; q < 4; q++) {
                    int c = sidx + q * 32;
                    fA[F_BE0 + p + c] = b0[c] + E0[tn * NU + c];
                    fA[F_BE1 + p + c] = b1[c] + E1[tn * NU + c];
                    fA[F_BE2 + p + c] = b2[c] + E2[tn * NU + c];
                }
            }
            // 3) update + layer0 for tile tc, step kc
            if (kc >= 0 && kc < NSTEPS) {
                const int t = 99 - kc;
                const float cf = fA[F_COEF + t], ia = fA[F_INVAS + t], bq = fA[F_BSQ + t];
                const float b30 = fA[F_B3], b31 = fA[F_B3 + 1];
                const float* be0n = &fA[F_BE0 + ((kc + 1) & 1) * 128];
                #pragma unroll
                for (int ri = 0; ri < 2; ri++) {
                    int r = sidx + ri * 32;
                    float p0 = b30, p1 = b31;
                    #pragma unroll
                    for (int g = 0; g < 4; g++) {
                        float2 v = fPP[tc * 256 + g * 64 + r];
                        p0 += v.x; p1 += v.y;
                    }
                    float2 xv = xreg[tc][ri];
                    float nx0 = (xv.x - cf * p0) * ia + bq * zuse[ri].x;
                    float nx1 = (xv.y - cf * p1) * ia + bq * zuse[ri].y;
                    if (kc == NSTEPS - 1) {
                        int smp = base + tc * 64 + r;
                        if (smp < BTOT) ((float2*)out)[smp] = make_float2(nx0, nx1);
                    } else {
                        xreg[tc][ri] = make_float2(nx0, nx1);
                        layer0_full(sb + SM_H1 + tc * 16384, xreg[tc][ri], fA, be0n, r);
                    }
                }
            }
            zuse[0] = znew[0];
            zuse[1] = znew[1];
        }
        __syncthreads();

        if (++sm3 == 3) { sm3 = 0; kdiv3++; }
    }
}

extern "C" void kernel_launch(void* const* d_in, const int* in_sizes, int n_in,
                              void* d_out, int out_size) {
    (void)in_sizes; (void)n_in; (void)out_size;
    const float* noise = (const float*)d_in[0];
    const float* z     = (const float*)d_in[1];
    const float* W0    = (const float*)d_in[2];
    const float* b0    = (const float*)d_in[3];
    const float* W1    = (const float*)d_in[4];
    const float* b1    = (const float*)d_in[5];
    const float* W2    = (const float*)d_in[6];
    const float* b2    = (const float*)d_in[7];
    const float* W3    = (const float*)d_in[8];
    const float* b3    = (const float*)d_in[9];
    const float* E0    = (const float*)d_in[10];
    const float* E1    = (const float*)d_in[11];
    const float* E2    = (const float*)d_in[12];
    float* out = (float*)d_out;

    cudaFuncSetAttribute(ddpm_kernel, cudaFuncAttributeMaxDynamicSharedMemorySize, SMEM_TOTAL);

    dim3 grid((BTOT + CTA_SAMPLES - 1) / CTA_SAMPLES);
    ddpm_kernel<<<grid, NTHREADS, SMEM_TOTAL>>>(noise, z, W0, b0, W1, b1, W2, b2,
                                                W3, b3, E0, E1, E2, out);
}

// round 6
// speedup vs baseline: 1.3637x; 1.3637x over previous
#include <cuda_runtime.h>
#include <cuda_bf16.h>
#include <cstdint>
#include <math.h>

#define NSTEPS 100
#define NU     128
#define BTOT   200000
#define NTHREADS 256
#define CTA_SAMPLES 128   // two 64-row tiles

// ---------------- SMEM layout ----------------
#define SM_H1A  0
#define SM_H1B  16384
#define SM_H2A  32768
#define SM_H2B  49152
#define SM_F32  65536

// float indices within fA
#define F_W3A   0
#define F_W3B   128
#define F_BE0   256      // [2][128] parity ping-pong
#define F_BE1   512
#define F_BE2   768
#define F_COEF  1024
#define F_INVAS 1124
#define F_BSQ   1224
#define F_B3    1324     // 2 floats (pad to 1328)
#define F_XS    1328     // float2[2 tiles][64] = 256 floats
#define F_PP    1584     // float2[2 tiles][4 warps][64] = 1024 floats
#define F_TOTAL 2608
#define SMEM_TOTAL (SM_F32 + F_TOTAL * 4)   // 75968 bytes

// ---------------- helpers ----------------
static __device__ __forceinline__ uint32_t smem_u32(const void* p) {
    uint32_t a;
    asm("{ .reg .u64 t; cvta.to.shared.u64 t, %1; cvt.u32.u64 %0, t; }" : "=r"(a) : "l"(p));
    return a;
}
static __device__ __forceinline__ uint32_t pack_bf16(float lo, float hi) {
    __nv_bfloat162 h = __floats2bfloat162_rn(lo, hi);
    return *reinterpret_cast<uint32_t*>(&h);
}

#define LDSM4(r0, r1, r2, r3, addr)                                              \
    asm volatile("ldmatrix.sync.aligned.m8n8.x4.shared.b16 {%0,%1,%2,%3}, [%4];" \
                 : "=r"(r0), "=r"(r1), "=r"(r2), "=r"(r3) : "r"(addr))

static __device__ __forceinline__ void mma16816(float c[4],
        uint32_t a0, uint32_t a1, uint32_t a2, uint32_t a3,
        uint32_t b0, uint32_t b1) {
    asm volatile(
        "mma.sync.aligned.m16n8k16.row.col.f32.bf16.bf16.f32 "
        "{%0,%1,%2,%3}, {%4,%5,%6,%7}, {%8,%9}, {%0,%1,%2,%3};"
        : "+f"(c[0]), "+f"(c[1]), "+f"(c[2]), "+f"(c[3])
        : "r"(a0), "r"(a1), "r"(a2), "r"(a3), "r"(b0), "r"(b1));
}
static __device__ __forceinline__ void mma16808(float c[4],
        uint32_t a0, uint32_t a1, uint32_t b0) {
    asm volatile(
        "mma.sync.aligned.m16n8k8.row.col.f32.bf16.bf16.f32 "
        "{%0,%1,%2,%3}, {%4,%5}, {%6}, {%0,%1,%2,%3};"
        : "+f"(c[0]), "+f"(c[1]), "+f"(c[2]), "+f"(c[3])
        : "r"(a0), "r"(a1), "r"(b0));
}

static __device__ __forceinline__ void sts32(uint32_t addr, uint32_t v) {
    asm volatile("st.shared.b32 [%0], %1;" :: "r"(addr), "r"(v) : "memory");
}
#define BAR_WG0() asm volatile("bar.sync 1, 128;" ::: "memory")
#define BAR_WG1() asm volatile("bar.sync 2, 128;" ::: "memory")

// ---- G1: dst = relu(src @ W + be), 64x128x128, warp owns 32 N-cols ----
static __device__ __forceinline__ void gemm_g1(
    uint32_t srcb, uint32_t dstb, const uint32_t (&B)[4][8][2], const float* be,
    int wg, uint32_t lrowoff, uint32_t r_lo, uint32_t khalf,
    uint32_t erow, uint32_t ecolq)
{
    #pragma unroll 1
    for (int mt = 0; mt < 4; mt++) {
        float c[4][4];
        #pragma unroll
        for (int nt = 0; nt < 4; nt++)
            #pragma unroll
            for (int q = 0; q < 4; q++) c[nt][q] = 0.f;

        const uint32_t abase = srcb + (uint32_t)mt * 4096 + lrowoff;
        #pragma unroll
        for (int kc = 0; kc < 8; kc++) {
            uint32_t a0, a1, a2, a3;
            LDSM4(a0, a1, a2, a3, abase + ((((uint32_t)(kc * 2) + khalf) ^ r_lo) << 4));
            #pragma unroll
            for (int nt = 0; nt < 4; nt++)
                mma16816(c[nt], a0, a1, a2, a3, B[nt][kc][0], B[nt][kc][1]);
        }
        const uint32_t row0 = (uint32_t)mt * 16 + erow;
        const uint32_t dst0 = dstb + row0 * 256;
        #pragma unroll
        for (int nt = 0; nt < 4; nt++) {
            int col = wg * 32 + nt * 8 + (int)ecolq * 2;
            float bea = be[col], beb = be[col + 1];
            float v0 = fmaxf(c[nt][0] + bea, 0.f);
            float v1 = fmaxf(c[nt][1] + beb, 0.f);
            float v2 = fmaxf(c[nt][2] + bea, 0.f);
            float v3 = fmaxf(c[nt][3] + beb, 0.f);
            uint32_t chunk = (uint32_t)(wg * 4 + nt);
            uint32_t a0addr = dst0 + ((chunk ^ erow) << 4) + ecolq * 4;
            sts32(a0addr,        pack_bf16(v0, v1));
            sts32(a0addr + 2048, pack_bf16(v2, v3));
        }
    }
}

// ---- L0: h1 = relu(x @ W0 + be0) via m16n8k8, A from fXS registers ----
static __device__ __forceinline__ void layer0_mma(
    const float2* xs, uint32_t dstb, const uint32_t (&B0)[4], const float* be0,
    int wg, int lane, uint32_t erow, uint32_t ecolq)
{
    const bool klane = ((lane & 3) == 0);
    #pragma unroll
    for (int mt = 0; mt < 4; mt++) {
        float c[4][4];
        #pragma unroll
        for (int nt = 0; nt < 4; nt++)
            #pragma unroll
            for (int q = 0; q < 4; q++) c[nt][q] = 0.f;

        int ra = mt * 16 + (lane >> 2);
        uint32_t a0 = 0u, a1 = 0u;
        if (klane) {
            float2 xa = xs[ra];
            float2 xb = xs[ra + 8];
            a0 = pack_bf16(xa.x, xa.y);
            a1 = pack_bf16(xb.x, xb.y);
        }
        #pragma unroll
        for (int nt = 0; nt < 4; nt++)
            mma16808(c[nt], a0, a1, B0[nt]);

        const uint32_t row0 = (uint32_t)mt * 16 + erow;
        const uint32_t dst0 = dstb + row0 * 256;
        #pragma unroll
        for (int nt = 0; nt < 4; nt++) {
            int col = wg * 32 + nt * 8 + (int)ecolq * 2;
            float bea = be0[col], beb = be0[col + 1];
            float v0 = fmaxf(c[nt][0] + bea, 0.f);
            float v1 = fmaxf(c[nt][1] + beb, 0.f);
            float v2 = fmaxf(c[nt][2] + bea, 0.f);
            float v3 = fmaxf(c[nt][3] + beb, 0.f);
            uint32_t chunk = (uint32_t)(wg * 4 + nt);
            uint32_t a0addr = dst0 + ((chunk ^ erow) << 4) + ecolq * 4;
            sts32(a0addr,        pack_bf16(v0, v1));
            sts32(a0addr + 2048, pack_bf16(v2, v3));
        }
    }
}

// ---- G2 + fused layer3 dot: per-warp pred partials -> fPPt ----
static __device__ __forceinline__ void gemm_g2(
    uint32_t srcb, const uint32_t (&B)[4][8][2], const float* be,
    const float* w3a, const float* w3b, float2* fPPt,
    int wg, uint32_t lrowoff, uint32_t r_lo, uint32_t khalf,
    uint32_t erow, uint32_t ecolq)
{
    #pragma unroll 1
    for (int mt = 0; mt < 4; mt++) {
        float c[4][4];
        #pragma unroll
        for (int nt = 0; nt < 4; nt++)
            #pragma unroll
            for (int q = 0; q < 4; q++) c[nt][q] = 0.f;

        const uint32_t abase = srcb + (uint32_t)mt * 4096 + lrowoff;
        #pragma unroll
        for (int kc = 0; kc < 8; kc++) {
            uint32_t a0, a1, a2, a3;
            LDSM4(a0, a1, a2, a3, abase + ((((uint32_t)(kc * 2) + khalf) ^ r_lo) << 4));
            #pragma unroll
            for (int nt = 0; nt < 4; nt++)
                mma16816(c[nt], a0, a1, a2, a3, B[nt][kc][0], B[nt][kc][1]);
        }

        float pA0 = 0.f, pA1 = 0.f, pB0 = 0.f, pB1 = 0.f;
        #pragma unroll
        for (int nt = 0; nt < 4; nt++) {
            int col = wg * 32 + nt * 8 + (int)ecolq * 2;
            float bea = be[col], beb = be[col + 1];
            float wa0 = w3a[col], wa1 = w3a[col + 1];
            float wb0 = w3b[col], wb1 = w3b[col + 1];
            float v0 = fmaxf(c[nt][0] + bea, 0.f);
            float v1 = fmaxf(c[nt][1] + beb, 0.f);
            float v2 = fmaxf(c[nt][2] + bea, 0.f);
            float v3 = fmaxf(c[nt][3] + beb, 0.f);
            pA0 = fmaf(v0, wa0, fmaf(v1, wa1, pA0));
            pA1 = fmaf(v0, wb0, fmaf(v1, wb1, pA1));
            pB0 = fmaf(v2, wa0, fmaf(v3, wa1, pB0));
            pB1 = fmaf(v2, wb0, fmaf(v3, wb1, pB1));
        }
        pA0 += __shfl_xor_sync(0xffffffffu, pA0, 1);
        pA1 += __shfl_xor_sync(0xffffffffu, pA1, 1);
        pB0 += __shfl_xor_sync(0xffffffffu, pB0, 1);
        pB1 += __shfl_xor_sync(0xffffffffu, pB1, 1);
        pA0 += __shfl_xor_sync(0xffffffffu, pA0, 2);
        pA1 += __shfl_xor_sync(0xffffffffu, pA1, 2);
        pB0 += __shfl_xor_sync(0xffffffffu, pB0, 2);
        pB1 += __shfl_xor_sync(0xffffffffu, pB1, 2);
        if (ecolq == 0) {
            int r = mt * 16 + (int)erow;
            fPPt[wg * 64 + r]     = make_float2(pA0, pA1);
            fPPt[wg * 64 + r + 8] = make_float2(pB0, pB1);
        }
    }
}

__global__ void __launch_bounds__(NTHREADS, 2)
ddpm_kernel(const float* __restrict__ noise, const float* __restrict__ z,
            const float* __restrict__ W0, const float* __restrict__ b0,
            const float* __restrict__ W1, const float* __restrict__ b1,
            const float* __restrict__ W2, const float* __restrict__ b2,
            const float* __restrict__ W3, const float* __restrict__ b3,
            const float* __restrict__ E0, const float* __restrict__ E1,
            const float* __restrict__ E2, float* __restrict__ out)
{
    extern __shared__ char smem_raw[];
    const uint32_t sb = smem_u32(smem_raw);
    float* fA = (float*)(smem_raw + SM_F32);
    float2* fXS = (float2*)&fA[F_XS];
    float2* fPP = (float2*)&fA[F_PP];

    const int tid  = threadIdx.x;
    const int lane = tid & 31;
    const int wid  = tid >> 5;
    const bool isWG0 = (wid < 4);
    const int wg   = wid & 3;
    const int base = blockIdx.x * CTA_SAMPLES;

    // ---- prologue ----
    if (tid < 128) {
        fA[F_W3A + tid] = W3[2 * tid];
        fA[F_W3B + tid] = W3[2 * tid + 1];
        fA[F_BE0 + tid] = b0[tid] + E0[99 * NU + tid];  // k=0 (t=99), parity 0
        fA[F_BE1 + tid] = b1[tid] + E1[99 * NU + tid];
        fA[F_BE2 + tid] = b2[tid] + E2[99 * NU + tid];
        // x init: fXS flat index = tile*64+row = tid
        int smp = base + tid;
        fXS[tid] = (smp < BTOT) ? ((const float2*)noise)[smp] : make_float2(0.f, 0.f);
    }
    if (tid < 2) fA[F_B3 + tid] = b3[tid];
    if (tid == 0) {
        double prod = 1.0;
        for (int t = 0; t < NSTEPS; t++) {
            double xl = -6.0 + 12.0 * (double)t / 99.0;
            double beta = (1.0 / (1.0 + exp(-xl))) * (0.005 - 1e-5) + 1e-5;
            double alpha = 1.0 - beta;
            prod *= alpha;
            fA[F_COEF + t]  = (float)(beta / sqrt(1.0 - prod));
            fA[F_INVAS + t] = (float)(1.0 / sqrt(alpha));
            fA[F_BSQ + t]   = (float)sqrt(beta);
        }
    }

    // ---- weight fragments ----
    uint32_t Bw[4][8][2];   // WG0: W1, WG1: W2
    uint32_t B0f[4] = {0u, 0u, 0u, 0u};  // WG0 only: W0 (k=0,1), lanes lane%4==0
    {
        const float* Wsrc = isWG0 ? W1 : W2;
        const int n0 = wg * 32 + (lane >> 2);
        const int kb2 = (lane & 3) * 2;
        #pragma unroll
        for (int nt = 0; nt < 4; nt++) {
            int n = n0 + nt * 8;
            #pragma unroll
            for (int kc = 0; kc < 8; kc++) {
                int k0 = kc * 16 + kb2;
                Bw[nt][kc][0] = pack_bf16(Wsrc[k0 * NU + n],       Wsrc[(k0 + 1) * NU + n]);
                Bw[nt][kc][1] = pack_bf16(Wsrc[(k0 + 8) * NU + n], Wsrc[(k0 + 9) * NU + n]);
            }
        }
        if (isWG0 && (lane & 3) == 0) {
            #pragma unroll
            for (int nt = 0; nt < 4; nt++) {
                int n = n0 + nt * 8;
                B0f[nt] = pack_bf16(W0[n], W0[NU + n]);
            }
        }
    }

    // per-lane constants
    const uint32_t r_lo    = (uint32_t)(lane & 7);
    const uint32_t half_l  = (uint32_t)((lane >> 3) & 1);
    const uint32_t khalf   = (uint32_t)(lane >> 4);
    const uint32_t lrowoff = (half_l * 8 + r_lo) * 256;
    const uint32_t erow    = (uint32_t)(lane >> 2);
    const uint32_t ecolq   = (uint32_t)(lane & 3);

    __syncthreads();

    // ---- prime: WG0 runs tile b through L0+G1 at k=0 ----
    if (isWG0) {
        layer0_mma(&fXS[64], sb + SM_H1B, B0f, &fA[F_BE0], wg, lane, erow, ecolq);
        BAR_WG0();
        gemm_g1(sb + SM_H1B, sb + SM_H2B, Bw, &fA[F_BE1], wg,
                lrowoff, r_lo, khalf, erow, ecolq);
    }
    __syncthreads();

    // ---- main loop: per step, slotA then slotB ----
    #pragma unroll 1
    for (int k = 0; k < NSTEPS; k++) {
        const int t    = 99 - k;
        const int par  = k & 1;
        const bool last = (k == NSTEPS - 1);

        // ===== slotA: WG0: L0(a,k)+G1(a,k) ; WG1: G2(b,k)+update(b,k) + prefetch(k+1) =====
        if (isWG0) {
            layer0_mma(&fXS[0], sb + SM_H1A, B0f, &fA[F_BE0 + par * 128],
                       wg, lane, erow, ecolq);
            BAR_WG0();
            gemm_g1(sb + SM_H1A, sb + SM_H2A, Bw, &fA[F_BE1 + par * 128], wg,
                    lrowoff, r_lo, khalf, erow, ecolq);
        } else {
            const int tid2 = tid - 128;
            // z for this slot's update (tile b)
            float2 zv = make_float2(0.f, 0.f);
            int smpB = base + 64 + (tid2 & 63);
            if (tid2 < 64 && smpB < BTOT)
                zv = ((const float2*)z)[(size_t)k * BTOT + smpB];
            // prefetch step-(k+1) tables into parity !par
            if (!last) {
                int tn = t - 1, pn = (par ^ 1) * 128;
                fA[F_BE0 + pn + tid2] = b0[tid2] + E0[tn * NU + tid2];
                fA[F_BE1 + pn + tid2] = b1[tid2] + E1[tn * NU + tid2];
                fA[F_BE2 + pn + tid2] = b2[tid2] + E2[tn * NU + tid2];
            }
            gemm_g2(sb + SM_H2B, Bw, &fA[F_BE2 + par * 128],
                    &fA[F_W3A], &fA[F_W3B], &fPP[256], wg,
                    lrowoff, r_lo, khalf, erow, ecolq);
            BAR_WG1();
            if (tid2 < 64) {
                int r = tid2;
                float p0 = fA[F_B3], p1 = fA[F_B3 + 1];
                #pragma unroll
                for (int g = 0; g < 4; g++) {
                    float2 v = fPP[256 + g * 64 + r];
                    p0 += v.x; p1 += v.y;
                }
                float cf = fA[F_COEF + t], ia = fA[F_INVAS + t], bq = fA[F_BSQ + t];
                float2 xv = fXS[64 + r];
                float nx0 = (xv.x - cf * p0) * ia + bq * zv.x;
                float nx1 = (xv.y - cf * p1) * ia + bq * zv.y;
                if (last) {
                    if (smpB < BTOT) ((float2*)out)[smpB] = make_float2(nx0, nx1);
                } else {
                    fXS[64 + r] = make_float2(nx0, nx1);
                }
            }
        }
        __syncthreads();

        // ===== slotB: WG0: L0(b,k+1)+G1(b,k+1) ; WG1: G2(a,k)+update(a,k) =====
        if (isWG0) {
            if (!last) {
                layer0_mma(&fXS[64], sb + SM_H1B, B0f, &fA[F_BE0 + (par ^ 1) * 128],
                           wg, lane, erow, ecolq);
                BAR_WG0();
                gemm_g1(sb + SM_H1B, sb + SM_H2B, Bw, &fA[F_BE1 + (par ^ 1) * 128], wg,
                        lrowoff, r_lo, khalf, erow, ecolq);
            }
        } else {
            const int tid2 = tid - 128;
            float2 zv = make_float2(0.f, 0.f);
            int smpA = base + (tid2 & 63);
            if (tid2 < 64 && smpA < BTOT)
                zv = ((const float2*)z)[(size_t)k * BTOT + smpA];
            gemm_g2(sb + SM_H2A, Bw, &fA[F_BE2 + par * 128],
                    &fA[F_W3A], &fA[F_W3B], &fPP[0], wg,
                    lrowoff, r_lo, khalf, erow, ecolq);
            BAR_WG1();
            if (tid2 < 64) {
                int r = tid2;
                float p0 = fA[F_B3], p1 = fA[F_B3 + 1];
                #pragma unroll
                for (int g = 0; g < 4; g++) {
                    float2 v = fPP[g * 64 + r];
                    p0 += v.x; p1 += v.y;
                }
                float cf = fA[F_COEF + t], ia = fA[F_INVAS + t], bq = fA[F_BSQ + t];
                float2 xv = fXS[r];
                float nx0 = (xv.x - cf * p0) * ia + bq * zv.x;
                float nx1 = (xv.y - cf * p1) * ia + bq * zv.y;
                if (last) {
                    if (smpA < BTOT) ((float2*)out)[smpA] = make_float2(nx0, nx1);
                } else {
                    fXS[r] = make_float2(nx0, nx1);
                }
            }
        }
        __syncthreads();
    }
}

extern "C" void kernel_launch(void* const* d_in, const int* in_sizes, int n_in,
                              void* d_out, int out_size) {
    (void)in_sizes; (void)n_in; (void)out_size;
    const float* noise = (const float*)d_in[0];
    const float* z     = (const float*)d_in[1];
    const float* W0    = (const float*)d_in[2];
    const float* b0    = (const float*)d_in[3];
    const float* W1    = (const float*)d_in[4];
    const float* b1    = (const float*)d_in[5];
    const float* W2    = (const float*)d_in[6];
    const float* b2    = (const float*)d_in[7];
    const float* W3    = (const float*)d_in[8];
    const float* b3    = (const float*)d_in[9];
    const float* E0    = (const float*)d_in[10];
    const float* E1    = (const float*)d_in[11];
    const float* E2    = (const float*)d_in[12];
    float* out = (float*)d_out;

    cudaFuncSetAttribute(ddpm_kernel, cudaFuncAttributeMaxDynamicSharedMemorySize, SMEM_TOTAL);

    dim3 grid((BTOT + CTA_SAMPLES - 1) / CTA_SAMPLES);
    ddpm_kernel<<<grid, NTHREADS, SMEM_TOTAL>>>(noise, z, W0, b0, W1, b1, W2, b2,
                                                W3, b3, E0, E1, E2, out);
}